// round 1
// baseline (speedup 1.0000x reference)
#include <cuda_runtime.h>
#include <math.h>

#define NN 100000
#define NE 3200000
#define FIN 128
#define RS 16          // padded row stride for 10-dim vectors
#define NB 1000

// Scratch (allocation-free: __device__ globals)
static __device__ float g_xa[NN * RS];    // x @ W1[:128]   (self part, L1)
static __device__ float g_xb[NN * RS];    // x @ W1[128:]   (neighbor part, L1)
static __device__ float g_agg1[NN * RS];  // edge-summed xb
static __device__ float g_h1a[NN * RS];   // h1 @ W2[:10]
static __device__ float g_h1b[NN * RS];   // h1 @ W2[10:]
static __device__ float g_agg2[NN * RS];  // edge-summed h1b
static __device__ float g_cnt[NN];        // in-degree (float)
static __device__ float g_pool[NB * RS];  // batch pool sums
static __device__ float g_pcnt[NB];       // nodes per graph

// ---------------------------------------------------------------------------
__global__ void k_zero() {
    int tid = blockIdx.x * blockDim.x + threadIdx.x;
    int stride = gridDim.x * blockDim.x;
    for (int i = tid; i < NN * RS; i += stride) { g_agg1[i] = 0.f; g_agg2[i] = 0.f; }
    for (int i = tid; i < NN; i += stride) g_cnt[i] = 0.f;
    for (int i = tid; i < NB * RS; i += stride) g_pool[i] = 0.f;
    for (int i = tid; i < NB; i += stride) g_pcnt[i] = 0.f;
}

// ---------------------------------------------------------------------------
// Layer-1 projection: warp per node, weights resident in registers.
// xa[n] = x[n] @ W1[0:128, :], xb[n] = x[n] @ W1[128:256, :]
__global__ __launch_bounds__(256) void k_gemm1(const float* __restrict__ x,
                                               const float* __restrict__ W1) {
    const int lane = threadIdx.x & 31;
    const int warp = (blockIdx.x * blockDim.x + threadIdx.x) >> 5;

    float wa[4][10], wb[4][10];
#pragma unroll
    for (int j = 0; j < 4; j++) {
        int f = lane + 32 * j;
#pragma unroll
        for (int o = 0; o < 10; o++) {
            wa[j][o] = __ldg(&W1[f * 10 + o]);
            wb[j][o] = __ldg(&W1[(f + 128) * 10 + o]);
        }
    }

    const int nbase = warp * 8;
#pragma unroll 1
    for (int ni = 0; ni < 8; ni++) {
        int n = nbase + ni;
        if (n >= NN) return;
        const float* xr = x + (size_t)n * FIN;
        float acc[20];
#pragma unroll
        for (int o = 0; o < 20; o++) acc[o] = 0.f;
#pragma unroll
        for (int j = 0; j < 4; j++) {
            float xv = xr[lane + 32 * j];
#pragma unroll
            for (int o = 0; o < 10; o++) {
                acc[o]      += xv * wa[j][o];
                acc[10 + o] += xv * wb[j][o];
            }
        }
#pragma unroll
        for (int off = 16; off; off >>= 1)
#pragma unroll
            for (int o = 0; o < 20; o++)
                acc[o] += __shfl_xor_sync(0xffffffffu, acc[o], off);
        if (lane == 0) {
            float* pa = g_xa + n * RS;
            float* pb = g_xb + n * RS;
#pragma unroll
            for (int o = 0; o < 10; o++) { pa[o] = acc[o]; pb[o] = acc[10 + o]; }
            pb[10] = 0.f; pb[11] = 0.f;   // pad so vector REDs add zero
        }
    }
}

// ---------------------------------------------------------------------------
__device__ __forceinline__ void red_v4(float* p, float a, float b, float c, float d) {
    asm volatile("red.global.add.v4.f32 [%0], {%1,%2,%3,%4};"
                 :: "l"(p), "f"(a), "f"(b), "f"(c), "f"(d) : "memory");
}

// Edge pass 1: agg1[dst] += xb[src]; cnt[dst] += 1
__global__ __launch_bounds__(256) void k_edge1(const int* __restrict__ src,
                                               const int* __restrict__ dst) {
    int e = blockIdx.x * blockDim.x + threadIdx.x;
    if (e >= NE) return;
    int s = src[e], d = dst[e];
    const float4* vp = (const float4*)(g_xb + (size_t)s * RS);
    float4 v0 = vp[0], v1 = vp[1], v2 = vp[2];
    float* op = g_agg1 + (size_t)d * RS;
    red_v4(op,     v0.x, v0.y, v0.z, v0.w);
    red_v4(op + 4, v1.x, v1.y, v1.z, v1.w);
    red_v4(op + 8, v2.x, v2.y, v2.z, v2.w);   // elems 10,11 are zero pad
    atomicAdd(&g_cnt[d], 1.0f);
}

// Edge pass 2: agg2[dst] += h1b[src]
__global__ __launch_bounds__(256) void k_edge2(const int* __restrict__ src,
                                               const int* __restrict__ dst) {
    int e = blockIdx.x * blockDim.x + threadIdx.x;
    if (e >= NE) return;
    int s = src[e], d = dst[e];
    const float4* vp = (const float4*)(g_h1b + (size_t)s * RS);
    float4 v0 = vp[0], v1 = vp[1], v2 = vp[2];
    float* op = g_agg2 + (size_t)d * RS;
    red_v4(op,     v0.x, v0.y, v0.z, v0.w);
    red_v4(op + 4, v1.x, v1.y, v1.z, v1.w);
    red_v4(op + 8, v2.x, v2.y, v2.z, v2.w);
}

// ---------------------------------------------------------------------------
// h1 = relu(xa + agg1/cnt); h1a = h1 @ W2[:10]; h1b = h1 @ W2[10:]
__global__ __launch_bounds__(256) void k_node2(const float* __restrict__ W2) {
    __shared__ float sw[200];
    if (threadIdx.x < 200) sw[threadIdx.x] = W2[threadIdx.x];
    __syncthreads();
    int n = blockIdx.x * blockDim.x + threadIdx.x;
    if (n >= NN) return;
    float c = g_cnt[n];
    float inv = c > 0.f ? 1.f / c : 0.f;
    float h[10];
#pragma unroll
    for (int o = 0; o < 10; o++)
        h[o] = fmaxf(g_xa[n * RS + o] + g_agg1[n * RS + o] * inv, 0.f);
    float a[10], b[10];
#pragma unroll
    for (int o = 0; o < 10; o++) { a[o] = 0.f; b[o] = 0.f; }
#pragma unroll
    for (int k = 0; k < 10; k++)
#pragma unroll
        for (int o = 0; o < 10; o++) {
            a[o] += h[k] * sw[k * 10 + o];
            b[o] += h[k] * sw[(k + 10) * 10 + o];
        }
#pragma unroll
    for (int o = 0; o < 10; o++) { g_h1a[n * RS + o] = a[o]; g_h1b[n * RS + o] = b[o]; }
    g_h1b[n * RS + 10] = 0.f; g_h1b[n * RS + 11] = 0.f;
}

// ---------------------------------------------------------------------------
// h2 = h1a + agg2/cnt; pool by (sorted) batch id with warp aggregation.
__global__ __launch_bounds__(256) void k_final(const int* __restrict__ batch) {
    int n = blockIdx.x * blockDim.x + threadIdx.x;
    if (n >= NN) return;            // NN % 32 == 0: whole warps exit together
    int lane = threadIdx.x & 31;
    float c = g_cnt[n];
    float inv = c > 0.f ? 1.f / c : 0.f;
    float h[10];
#pragma unroll
    for (int o = 0; o < 10; o++)
        h[o] = g_h1a[n * RS + o] + g_agg2[n * RS + o] * inv;
    int b = batch[n];
    int b0 = __shfl_sync(0xffffffffu, b, 0);
    bool uni = __all_sync(0xffffffffu, b == b0);
    if (uni) {
#pragma unroll
        for (int off = 16; off; off >>= 1)
#pragma unroll
            for (int o = 0; o < 10; o++)
                h[o] += __shfl_xor_sync(0xffffffffu, h[o], off);
        if (lane == 0) {
            float* pp = g_pool + b * RS;
            red_v4(pp,     h[0], h[1], h[2], h[3]);
            red_v4(pp + 4, h[4], h[5], h[6], h[7]);
            red_v4(pp + 8, h[8], h[9], 0.f, 0.f);
            atomicAdd(&g_pcnt[b], 32.f);
        }
    } else {
        float* pp = g_pool + b * RS;
#pragma unroll
        for (int o = 0; o < 10; o++) atomicAdd(&pp[o], h[o]);
        atomicAdd(&g_pcnt[b], 1.f);
    }
}

// ---------------------------------------------------------------------------
__global__ void k_head(const float* __restrict__ Wfc, float* __restrict__ out) {
    int b = blockIdx.x * blockDim.x + threadIdx.x;
    if (b >= NB) return;
    float inv = 1.f / fmaxf(g_pcnt[b], 1.f);
    float v = 0.f;
#pragma unroll
    for (int o = 0; o < 10; o++)
        v += g_pool[b * RS + o] * inv * __ldg(&Wfc[o]);
    out[b] = 1.f / (1.f + expf(-v));
}

// ---------------------------------------------------------------------------
extern "C" void kernel_launch(void* const* d_in, const int* in_sizes, int n_in,
                              void* d_out, int out_size) {
    const float* x    = (const float*)d_in[0];
    const int*   ei   = (const int*)d_in[1];   // [2, E]
    const int*   batch= (const int*)d_in[2];
    const float* W1   = (const float*)d_in[3]; // [256,10]
    const float* W2   = (const float*)d_in[4]; // [20,10]
    const float* Wfc  = (const float*)d_in[5]; // [10,1]
    float* out = (float*)d_out;

    const int* src = ei;
    const int* dst = ei + NE;

    k_zero<<<2048, 256>>>();
    k_gemm1<<<(12500 + 7) / 8, 256>>>(x, W1);          // 12500 warps, 8 nodes each
    k_edge1<<<(NE + 255) / 256, 256>>>(src, dst);
    k_node2<<<(NN + 255) / 256, 256>>>(W2);
    k_edge2<<<(NE + 255) / 256, 256>>>(src, dst);
    k_final<<<(NN + 255) / 256, 256>>>(batch);
    k_head<<<(NB + 255) / 256, 256>>>(Wfc, out);
}

// round 2
// speedup vs baseline: 1.0514x; 1.0514x over previous
#include <cuda_runtime.h>
#include <math.h>

#define NN 100000
#define NE 3200000
#define FIN 128
#define RS 16          // padded row stride for 10-dim vectors
#define NB 1000

// Scratch (allocation-free: __device__ globals)
static __device__ float g_xa[NN * RS];    // x @ W1[:128]   (self part)
static __device__ float g_xb[NN * RS];    // x @ W1[128:]   (neighbor part; [10]=1 for degree)
static __device__ float g_agg1[NN * RS];  // edge-summed xb ([10] = in-degree)
static __device__ float g_h1a[NN * RS];   // h1 @ W2[:10]   ([10] = 1/deg)
static __device__ float g_h1b[NN * RS];   // h1 @ W2[10:]
static __device__ float g_agg2[NN * RS];  // edge-summed h1b
static __device__ float g_pool[NB * RS];  // batch pool sums ([10] = node count)

// ---------------------------------------------------------------------------
__global__ void k_zero() {
    int tid = blockIdx.x * blockDim.x + threadIdx.x;
    int stride = gridDim.x * blockDim.x;
    float4 z = make_float4(0.f, 0.f, 0.f, 0.f);
    float4* a1 = (float4*)g_agg1;
    float4* a2 = (float4*)g_agg2;
    for (int i = tid; i < NN * RS / 4; i += stride) { a1[i] = z; a2[i] = z; }
    float4* pp = (float4*)g_pool;
    for (int i = tid; i < NB * RS / 4; i += stride) pp[i] = z;
}

// ---------------------------------------------------------------------------
// Layer-1 projection: warp per 8 nodes, weights resident in registers,
// register-permuted split reduction (30 shuffles/node instead of 100).
//
// Register r on a lane maps to output index:
//   r < 10 : out = 10*b4 + ((r + 5*b3) % 10)
//   r >= 10: out = 10*(1-b4) + (((r-10) + 5*b3) % 10)
// where b4 = lane bit4, b3 = lane bit3. Outputs 0-9 -> xa, 10-19 -> xb.
__global__ __launch_bounds__(256) void k_gemm1(const float* __restrict__ x,
                                               const float* __restrict__ W1) {
    const int lane = threadIdx.x & 31;
    const int warp = (blockIdx.x * blockDim.x + threadIdx.x) >> 5;
    if (warp >= NN / 8) return;
    const int b4 = (lane >> 4) & 1;
    const int b3 = (lane >> 3) & 1;

    // load permuted weights: lane covers features f = lane*4 .. lane*4+3
    float w[4][20];
#pragma unroll
    for (int j = 0; j < 4; j++) {
        int f = lane * 4 + j;
#pragma unroll
        for (int r = 0; r < 20; r++) {
            int o = (r < 10) ? (10 * b4 + ((r + 5 * b3) % 10))
                             : (10 * (1 - b4) + (((r - 10) + 5 * b3) % 10));
            w[j][r] = __ldg((o < 10) ? &W1[f * 10 + o] : &W1[(f + 128) * 10 + (o - 10)]);
        }
    }

    const int nbase = warp * 8;
#pragma unroll 1
    for (int ni = 0; ni < 8; ni++) {
        int n = nbase + ni;
        float4 xv = *(const float4*)(x + (size_t)n * FIN + lane * 4);
        float xs[4] = {xv.x, xv.y, xv.z, xv.w};
        float acc[20];
#pragma unroll
        for (int r = 0; r < 20; r++) acc[r] = 0.f;
#pragma unroll
        for (int j = 0; j < 4; j++)
#pragma unroll
            for (int r = 0; r < 20; r++) acc[r] += xs[j] * w[j][r];

        // split reduce: 20 -> 10 (xor16), 10 -> 5 (xor8), butterfly 5 (xor4,2,1)
#pragma unroll
        for (int i = 0; i < 10; i++) acc[i] += __shfl_xor_sync(0xffffffffu, acc[i + 10], 16);
#pragma unroll
        for (int i = 0; i < 5; i++)  acc[i] += __shfl_xor_sync(0xffffffffu, acc[i + 5], 8);
#pragma unroll
        for (int off = 4; off; off >>= 1)
#pragma unroll
            for (int i = 0; i < 5; i++)
                acc[i] += __shfl_xor_sync(0xffffffffu, acc[i], off);

        // lane 0: out0-4 -> xa[0..4]; lane 8: out5-9 -> xa[5..9]
        // lane16: out10-14 -> xb[0..4]; lane24: out15-19 -> xb[5..9] + pads
        if ((lane & 7) == 0) {
            if (lane == 0) {
#pragma unroll
                for (int i = 0; i < 5; i++) g_xa[n * RS + i] = acc[i];
            } else if (lane == 8) {
#pragma unroll
                for (int i = 0; i < 5; i++) g_xa[n * RS + 5 + i] = acc[i];
            } else if (lane == 16) {
#pragma unroll
                for (int i = 0; i < 5; i++) g_xb[n * RS + i] = acc[i];
            } else {
#pragma unroll
                for (int i = 0; i < 5; i++) g_xb[n * RS + 5 + i] = acc[i];
                g_xb[n * RS + 10] = 1.0f;   // degree counter rides the vector RED
                g_xb[n * RS + 11] = 0.0f;
            }
        }
    }
}

// ---------------------------------------------------------------------------
__device__ __forceinline__ void red_v4(float* p, float a, float b, float c, float d) {
    asm volatile("red.global.add.v4.f32 [%0], {%1,%2,%3,%4};"
                 :: "l"(p), "f"(a), "f"(b), "f"(c), "f"(d) : "memory");
}

// Edge pass: agg[dst] += buf[src], 2 edges per thread for MLP.
template <int PASS>
__global__ __launch_bounds__(256) void k_edge(const int* __restrict__ src,
                                              const int* __restrict__ dst) {
    const float* buf = (PASS == 0) ? g_xb : g_h1b;
    float* agg = (PASS == 0) ? g_agg1 : g_agg2;
    int t = blockIdx.x * blockDim.x + threadIdx.x;
    if (t >= NE / 2) return;
    int2 s2 = __ldg((const int2*)src + t);
    int2 d2 = __ldg((const int2*)dst + t);
    const float4* vp0 = (const float4*)(buf + (size_t)s2.x * RS);
    const float4* vp1 = (const float4*)(buf + (size_t)s2.y * RS);
    float4 a0 = vp0[0], a1 = vp0[1], a2 = vp0[2];
    float4 b0 = vp1[0], b1 = vp1[1], b2 = vp1[2];
    float* op0 = agg + (size_t)d2.x * RS;
    float* op1 = agg + (size_t)d2.y * RS;
    red_v4(op0,     a0.x, a0.y, a0.z, a0.w);
    red_v4(op0 + 4, a1.x, a1.y, a1.z, a1.w);
    red_v4(op0 + 8, a2.x, a2.y, a2.z, a2.w);
    red_v4(op1,     b0.x, b0.y, b0.z, b0.w);
    red_v4(op1 + 4, b1.x, b1.y, b1.z, b1.w);
    red_v4(op1 + 8, b2.x, b2.y, b2.z, b2.w);
}

// ---------------------------------------------------------------------------
// h1 = relu(xa + agg1/deg); h1a = h1 @ W2[:10] (+inv in pad); h1b = h1 @ W2[10:]
__global__ __launch_bounds__(256) void k_node2(const float* __restrict__ W2) {
    __shared__ float sw[200];
    if (threadIdx.x < 200) sw[threadIdx.x] = W2[threadIdx.x];
    __syncthreads();
    int n = blockIdx.x * blockDim.x + threadIdx.x;
    if (n >= NN) return;
    const float4* xr = (const float4*)(g_xa + n * RS);
    const float4* gr = (const float4*)(g_agg1 + n * RS);
    float4 x0 = xr[0], x1 = xr[1], x2 = xr[2];
    float4 g0 = gr[0], g1 = gr[1], g2 = gr[2];
    float c = g2.z;                      // degree accumulated in pad slot 10
    float inv = c > 0.f ? 1.f / c : 0.f;
    float h[10];
    h[0] = fmaxf(x0.x + g0.x * inv, 0.f); h[1] = fmaxf(x0.y + g0.y * inv, 0.f);
    h[2] = fmaxf(x0.z + g0.z * inv, 0.f); h[3] = fmaxf(x0.w + g0.w * inv, 0.f);
    h[4] = fmaxf(x1.x + g1.x * inv, 0.f); h[5] = fmaxf(x1.y + g1.y * inv, 0.f);
    h[6] = fmaxf(x1.z + g1.z * inv, 0.f); h[7] = fmaxf(x1.w + g1.w * inv, 0.f);
    h[8] = fmaxf(x2.x + g2.x * inv, 0.f); h[9] = fmaxf(x2.y + g2.y * inv, 0.f);
    float a[10], b[10];
#pragma unroll
    for (int o = 0; o < 10; o++) { a[o] = 0.f; b[o] = 0.f; }
#pragma unroll
    for (int k = 0; k < 10; k++)
#pragma unroll
        for (int o = 0; o < 10; o++) {
            a[o] += h[k] * sw[k * 10 + o];
            b[o] += h[k] * sw[(k + 10) * 10 + o];
        }
    float4* pa = (float4*)(g_h1a + n * RS);
    float4* pb = (float4*)(g_h1b + n * RS);
    pa[0] = make_float4(a[0], a[1], a[2], a[3]);
    pa[1] = make_float4(a[4], a[5], a[6], a[7]);
    pa[2] = make_float4(a[8], a[9], inv, 0.f);     // stash inv for k_final
    pb[0] = make_float4(b[0], b[1], b[2], b[3]);
    pb[1] = make_float4(b[4], b[5], b[6], b[7]);
    pb[2] = make_float4(b[8], b[9], 0.f, 0.f);
}

// ---------------------------------------------------------------------------
// h2 = h1a + agg2/deg; pool by (sorted) batch id with warp aggregation.
__global__ __launch_bounds__(256) void k_final(const int* __restrict__ batch) {
    int n = blockIdx.x * blockDim.x + threadIdx.x;
    if (n >= NN) return;            // NN % 32 == 0: whole warps exit together
    int lane = threadIdx.x & 31;
    const float4* ar = (const float4*)(g_h1a + n * RS);
    const float4* gr = (const float4*)(g_agg2 + n * RS);
    float4 a0 = ar[0], a1 = ar[1], a2 = ar[2];
    float4 g0 = gr[0], g1 = gr[1], g2 = gr[2];
    float inv = a2.z;
    float h[10];
    h[0] = a0.x + g0.x * inv; h[1] = a0.y + g0.y * inv;
    h[2] = a0.z + g0.z * inv; h[3] = a0.w + g0.w * inv;
    h[4] = a1.x + g1.x * inv; h[5] = a1.y + g1.y * inv;
    h[6] = a1.z + g1.z * inv; h[7] = a1.w + g1.w * inv;
    h[8] = a2.x + g2.x * inv; h[9] = a2.y + g2.y * inv;
    int b = batch[n];
    int b0 = __shfl_sync(0xffffffffu, b, 0);
    bool uni = __all_sync(0xffffffffu, b == b0);
    if (uni) {
#pragma unroll
        for (int off = 16; off; off >>= 1)
#pragma unroll
            for (int o = 0; o < 10; o++)
                h[o] += __shfl_xor_sync(0xffffffffu, h[o], off);
        if (lane == 0) {
            float* pp = g_pool + b * RS;
            red_v4(pp,     h[0], h[1], h[2], h[3]);
            red_v4(pp + 4, h[4], h[5], h[6], h[7]);
            red_v4(pp + 8, h[8], h[9], 32.f, 0.f);   // node count in pad
        }
    } else {
        float* pp = g_pool + b * RS;
#pragma unroll
        for (int o = 0; o < 10; o++) atomicAdd(&pp[o], h[o]);
        atomicAdd(&pp[10], 1.f);
    }
}

// ---------------------------------------------------------------------------
__global__ void k_head(const float* __restrict__ Wfc, float* __restrict__ out) {
    int b = blockIdx.x * blockDim.x + threadIdx.x;
    if (b >= NB) return;
    float inv = 1.f / fmaxf(g_pool[b * RS + 10], 1.f);
    float v = 0.f;
#pragma unroll
    for (int o = 0; o < 10; o++)
        v += g_pool[b * RS + o] * inv * __ldg(&Wfc[o]);
    out[b] = 1.f / (1.f + expf(-v));
}

// ---------------------------------------------------------------------------
extern "C" void kernel_launch(void* const* d_in, const int* in_sizes, int n_in,
                              void* d_out, int out_size) {
    const float* x    = (const float*)d_in[0];
    const int*   ei   = (const int*)d_in[1];   // [2, E]
    const int*   batch= (const int*)d_in[2];
    const float* W1   = (const float*)d_in[3]; // [256,10]
    const float* W2   = (const float*)d_in[4]; // [20,10]
    const float* Wfc  = (const float*)d_in[5]; // [10,1]
    float* out = (float*)d_out;

    const int* src = ei;
    const int* dst = ei + NE;

    k_zero<<<1024, 256>>>();
    k_gemm1<<<(NN / 8 + 7) / 8, 256>>>(x, W1);         // 12500 warps, 8 nodes each
    k_edge<0><<<(NE / 2 + 255) / 256, 256>>>(src, dst);
    k_node2<<<(NN + 255) / 256, 256>>>(W2);
    k_edge<1><<<(NE / 2 + 255) / 256, 256>>>(src, dst);
    k_final<<<(NN + 255) / 256, 256>>>(batch);
    k_head<<<(NB + 255) / 256, 256>>>(Wfc, out);
}